// round 11
// baseline (speedup 1.0000x reference)
#include <cuda_runtime.h>
#include <cuda_fp16.h>
#include <cstdint>

// Coords-weighted softmax attention via mma.sync m16n8k16 fp16 (sm_100 base ISA).
// R11 = R10 resubmitted unchanged (R10 bench died to a container/infra failure,
// same signature as R0; no kernel-side diagnostics).
// R10: QT=64, M=16/warp, __launch_bounds__(128,4) -> 4 CTAs/SM, 16 warps/SM,
//      single wave of 512 CTAs (no 2-vs-1 CTA imbalance).
//  - 1/8*log2(e) folded into Q before fp16 rounding; p = w * ex2(s).
//  - denominator on the (idle) FMA pipe: den += p terms; quad-reduced by shfl.
//  - V plain fp16 transposed [d][s]; w kept in smem per tile.

namespace {
constexpr int BH = 16, L = 2048, S = 2048, DD = 64;
constexpr int QT = 64;             // queries per CTA
constexpr int KT = 64;             // keys per tile
constexpr int NT = S / KT;         // 32
constexpr int NSTAGE = 3;

constexpr int ROWB = 144;          // smem row pitch bytes (128B data + 16B skew)

constexpr int KH_OFF = 0;
constexpr int VH_OFF = KH_OFF + KT * ROWB;    //  9216
constexpr int W_OFF  = VH_OFF + KT * ROWB;    // 18432
constexpr int STAGE  = W_OFF + KT * 4;        // 18688
constexpr int SM_BYTES = NSTAGE * STAGE;      // 56064 (x4 CTAs = 224K)

constexpr int KBLOCKS = BH * S * DD / 8 / 256;  // 1024 prep blocks for K
}

// prep scratch
__device__ __align__(16) __half gKh[BH * S * DD];
__device__ __align__(16) __half gVth[BH * DD * S];   // [h][d][s]

// ---------------- asm helpers ----------------
__device__ __forceinline__ uint32_t smem_u32(const void* p) {
    uint32_t a;
    asm("{ .reg .u64 t; cvta.to.shared.u64 t, %1; cvt.u32.u64 %0, t; }" : "=r"(a) : "l"(p));
    return a;
}
__device__ __forceinline__ float ex2f(float x) {
    float r;
    asm("ex2.approx.f32 %0, %1;" : "=f"(r) : "f"(x));
    return r;
}

#define MMA_F16(c, a, b0_, b1_)                                                    \
    asm volatile("mma.sync.aligned.m16n8k16.row.col.f32.f16.f16.f32 "              \
                 "{%0,%1,%2,%3},{%4,%5,%6,%7},{%8,%9},{%0,%1,%2,%3};"              \
                 : "+f"((c)[0]), "+f"((c)[1]), "+f"((c)[2]), "+f"((c)[3])          \
                 : "r"((a)[0]), "r"((a)[1]), "r"((a)[2]), "r"((a)[3]),             \
                   "r"(b0_), "r"(b1_))

#define LDSM4(r, addr)                                                             \
    asm volatile("ldmatrix.sync.aligned.m8n8.x4.shared.b16 {%0,%1,%2,%3}, [%4];"   \
                 : "=r"((r)[0]), "=r"((r)[1]), "=r"((r)[2]), "=r"((r)[3])          \
                 : "r"(addr))

#define CP16(dst, src)                                                             \
    asm volatile("cp.async.cg.shared.global [%0], [%1], 16;" :: "r"(dst), "l"(src))
#define CP_COMMIT() asm volatile("cp.async.commit_group;" ::: "memory")
#define CP_WAIT1()  asm volatile("cp.async.wait_group 1;" ::: "memory")
#define CP_WAIT0()  asm volatile("cp.async.wait_group 0;" ::: "memory")

// ldmatrix x4 lane address: 4 8x8 matrices (n0,k),(n0,k+8),(n0+8,k),(n0+8,k+8)
__device__ __forceinline__ uint32_t ldsm_addr(uint32_t base, int n0, int kel, int lane) {
    int gq = lane >> 3, lr = lane & 7;
    int row = n0 + lr + ((gq & 2) << 2);
    int col = kel + ((gq & 1) << 3);
    return base + row * ROWB + col * 2;
}

__device__ __forceinline__ uint32_t pack_h2(float x, float y) {
    __half2 t = __floats2half2_rn(x, y);
    return *reinterpret_cast<uint32_t*>(&t);
}

// ---------------- merged prep ----------------
// blocks [0, KBLOCKS):    K fp32 -> fp16 (8 elems/thread)
// blocks [KBLOCKS, +512): Vt[d][s] = fp16(V[s][d])
__global__ __launch_bounds__(256)
void prep_all(const float* __restrict__ K, const float* __restrict__ V)
{
    __shared__ float sm[64 * 65];

    if (blockIdx.x < KBLOCKS) {
        int idx = blockIdx.x * 256 + threadIdx.x;
        const float4* src = (const float4*)K + idx * 2;
        float4 a = src[0], b = src[1];
        uint4 o;
        o.x = pack_h2(a.x, a.y);
        o.y = pack_h2(a.z, a.w);
        o.z = pack_h2(b.x, b.y);
        o.w = pack_h2(b.z, b.w);
        *((uint4*)gKh + idx) = o;
        return;
    }

    int vb = blockIdx.x - KBLOCKS;          // 0..511
    int head = vb >> 5, s0 = (vb & 31) * 64;
    const float* src = V + (head * S + s0) * DD;
    for (int i = threadIdx.x; i < 1024; i += 256) {    // float4 index
        int r = i >> 4, c4 = (i & 15) * 4;
        float4 v = *(const float4*)(src + r * DD + c4);
        sm[(c4 + 0) * 65 + r] = v.x;
        sm[(c4 + 1) * 65 + r] = v.y;
        sm[(c4 + 2) * 65 + r] = v.z;
        sm[(c4 + 3) * 65 + r] = v.w;
    }
    __syncthreads();
    for (int i = threadIdx.x; i < 1024; i += 256) {
        int d = i >> 4, c4 = (i & 15) * 4;
        const float* row = &sm[d * 65 + c4];
        uint2 o;
        o.x = pack_h2(row[0], row[1]);
        o.y = pack_h2(row[2], row[3]);
        *(uint2*)(gVth + ((size_t)head * DD + d) * S + s0 + c4) = o;
    }
}

// ---------------- main kernel: 4 warps, M=16 rows per warp, QT=64 ----------------
__global__ __launch_bounds__(128, 4)
void attn_mma_kernel(const float* __restrict__ Q, const float* __restrict__ C,
                     float* __restrict__ O)
{
    extern __shared__ char smc[];
    const uint32_t sb = smem_u32(smc);
    const int tid  = threadIdx.x;
    const int lane = tid & 31;
    const int warp = tid >> 5;
    const int head = blockIdx.y;
    const int qtile = blockIdx.x;

    const int g  = lane >> 2;       // row within m8 group
    const int tq = lane & 3;        // column quad

    const int qrow = qtile * QT + warp * 16 + g;

    // ---- async tile loader (Kh, Vt, w) into stage t%3 ----
    auto issue = [&](int t) {
        const uint32_t st = sb + (t % NSTAGE) * STAGE;
        const int s0 = t * KT;
        const char* kh = (const char*)(gKh + (size_t)(head * S + s0) * DD);
        #pragma unroll
        for (int it = 0; it < 4; ++it) {
            int i = it * 128 + tid;                 // 0..511 16B chunks (K)
            uint32_t dst = (i >> 3) * ROWB + (i & 7) * 16;
            CP16(st + KH_OFF + dst, kh + i * 16);
        }
        #pragma unroll
        for (int it = 0; it < 4; ++it) {
            int i = it * 128 + tid;                 // 0..511 16B chunks (V)
            int d = i >> 3, c = i & 7;
            size_t vsrc = (((size_t)head * DD + d) * S + s0) * 2 + c * 16;
            uint32_t dst = d * ROWB + c * 16;
            CP16(st + VH_OFF + dst, (const char*)gVth + vsrc);
        }
        if (tid < KT) {
            int s = s0 + tid;
            float w = (s == 0) ? 0.f : fabsf(C[s] - C[s - 1]);
            *(float*)(smc + (t % NSTAGE) * STAGE + W_OFF + tid * 4) = w;
        }
    };

    issue(0); CP_COMMIT();

    // ---- Q A-fragments: fp32 global -> fp16 regs, 0.125*log2(e) folded ----
    uint32_t qh[4][4];
    {
        constexpr float SC = 0.125f * 1.4426950408889634f;
        const float* q0 = Q + (size_t)(head * L + qrow) * DD;
        const float* q8 = q0 + 8 * DD;
        #pragma unroll
        for (int ks = 0; ks < 4; ++ks) {
            int cb = ks * 16 + tq * 2;
            float2 a0 = *(const float2*)(q0 + cb);
            float2 a1 = *(const float2*)(q8 + cb);
            float2 a2 = *(const float2*)(q0 + cb + 8);
            float2 a3 = *(const float2*)(q8 + cb + 8);
            qh[ks][0] = pack_h2(a0.x * SC, a0.y * SC);
            qh[ks][1] = pack_h2(a1.x * SC, a1.y * SC);
            qh[ks][2] = pack_h2(a2.x * SC, a2.y * SC);
            qh[ks][3] = pack_h2(a3.x * SC, a3.y * SC);
        }
    }

    issue(1); CP_COMMIT();

    float o_acc[8][4];
    #pragma unroll
    for (int i = 0; i < 8; ++i)
        #pragma unroll
        for (int j = 0; j < 4; ++j) o_acc[i][j] = 0.f;
    float den0 = 0.f, den1 = 0.f;

    for (int t = 0; t < NT; ++t) {
        if (t == NT - 1) { CP_WAIT0(); } else { CP_WAIT1(); }
        __syncthreads();   // stage t ready, stage (t+2)%3 free

        const uint32_t st = sb + (t % NSTAGE) * STAGE;
        const float* wv = (const float*)(smc + (t % NSTAGE) * STAGE + W_OFF);

        #pragma unroll
        for (int kc = 0; kc < 4; ++kc) {
            // ---- GEMM1: scores (fp16, exp2 domain), keys [16kc,16kc+16) ----
            float sc0[4] = {0.f, 0.f, 0.f, 0.f};
            float sc1[4] = {0.f, 0.f, 0.f, 0.f};
            #pragma unroll
            for (int ks = 0; ks < 4; ++ks) {
                uint32_t bh[4];
                LDSM4(bh, ldsm_addr(st + KH_OFF, 16 * kc, ks * 16, lane));
                MMA_F16(sc0, qh[ks], bh[0], bh[1]);
                MMA_F16(sc1, qh[ks], bh[2], bh[3]);
            }

            // ---- p = w * ex2(s); den on FMA pipe; fp16 A-frag for GEMM2 ----
            uint32_t aH[4];
            {
                const int kb = 16 * kc;
                float2 w0 = *(const float2*)&wv[kb + tq * 2];
                float2 w1 = *(const float2*)&wv[kb + 8 + tq * 2];
                float p00 = w0.x * ex2f(sc0[0]);
                float p01 = w0.y * ex2f(sc0[1]);
                float p02 = w0.x * ex2f(sc0[2]);
                float p03 = w0.y * ex2f(sc0[3]);
                float p10 = w1.x * ex2f(sc1[0]);
                float p11 = w1.y * ex2f(sc1[1]);
                float p12 = w1.x * ex2f(sc1[2]);
                float p13 = w1.y * ex2f(sc1[3]);
                den0 += p00 + p01 + p10 + p11;   // row g
                den1 += p02 + p03 + p12 + p13;   // row g+8
                aH[0] = pack_h2(p00, p01);
                aH[1] = pack_h2(p02, p03);
                aH[2] = pack_h2(p10, p11);
                aH[3] = pack_h2(p12, p13);
            }

            // ---- GEMM2: O += P * Vt ----
            #pragma unroll
            for (int nd = 0; nd < 4; ++nd) {
                uint32_t vh[4];
                LDSM4(vh, ldsm_addr(st + VH_OFF, 16 * nd, 16 * kc, lane));
                MMA_F16(o_acc[2 * nd],     aH, vh[0], vh[1]);
                MMA_F16(o_acc[2 * nd + 1], aH, vh[2], vh[3]);
            }
        }

        if (t + 2 < NT) { issue(t + 2); CP_COMMIT(); }
    }

    // ---- denominator quad-reduce + store ----
    den0 += __shfl_xor_sync(0xffffffffu, den0, 1);
    den0 += __shfl_xor_sync(0xffffffffu, den0, 2);
    den1 += __shfl_xor_sync(0xffffffffu, den1, 1);
    den1 += __shfl_xor_sync(0xffffffffu, den1, 2);
    float inv0 = 1.0f / den0, inv1 = 1.0f / den1;

    float* dst0 = O + (size_t)(head * L + qrow) * DD;
    float* dst1 = dst0 + 8 * DD;
    #pragma unroll
    for (int nf = 0; nf < 8; ++nf) {
        int col = nf * 8 + tq * 2;
        float2 r0, r1;
        r0.x = o_acc[nf][0] * inv0; r0.y = o_acc[nf][1] * inv0;
        r1.x = o_acc[nf][2] * inv1; r1.y = o_acc[nf][3] * inv1;
        *(float2*)(dst0 + col) = r0;
        *(float2*)(dst1 + col) = r1;
    }
}

extern "C" void kernel_launch(void* const* d_in, const int* in_sizes, int n_in,
                              void* d_out, int out_size)
{
    const float* Q = (const float*)d_in[0];
    const float* K = (const float*)d_in[1];
    const float* V = (const float*)d_in[2];
    const float* C = (const float*)d_in[3];
    float* O = (float*)d_out;

    prep_all<<<KBLOCKS + 512, 256>>>(K, V);

    cudaFuncSetAttribute(attn_mma_kernel,
                         cudaFuncAttributeMaxDynamicSharedMemorySize, SM_BYTES);
    attn_mma_kernel<<<dim3(L / QT, BH), 128, SM_BYTES>>>(Q, C, O);
}

// round 12
// speedup vs baseline: 1.1433x; 1.1433x over previous
#include <cuda_runtime.h>
#include <cuda_fp16.h>
#include <cstdint>

// Coords-weighted softmax attention via mma.sync m16n8k16 fp16 (sm_100 base ISA).
// R12 = R9 base (M=32/warp, QT=128, 4 warps, 2 CTAs/SM -- LDSM economy wins per
// R11 post-mortem) with an instruction diet:
//  - KT=128 key tiles (16 tiles): half the barriers, 2-stage ping-pong (t&1).
//  - hoisted per-thread cp.async addressing (loop-invariant offsets).
//  - prefetch issued before compute each tile (stage freed at prior barrier).
//  - math unchanged from R9: 1/8*log2(e) folded into Q, p = ex2(s) in fp32,
//    w folded into V' = w*V, Vt row 64 = w -> denominator via one extra n=8 MMA.

namespace {
constexpr int BH = 16, L = 2048, S = 2048, DD = 64;
constexpr int QT = 128;            // queries per CTA
constexpr int KT = 128;            // keys per tile
constexpr int NT = S / KT;         // 16
constexpr int D2 = 72;             // Vt rows: 64 d + w row + 7 zero

constexpr int KROWB = 144;         // K smem pitch (128B data + 16B skew)
constexpr int VROWB = 272;         // V smem pitch (256B data + 16B skew)

constexpr int KH_OFF = 0;                      // 128 rows * 144
constexpr int VH_OFF = KT * KROWB;             // 18432
constexpr int STAGE  = VH_OFF + D2 * VROWB;    // 18432 + 19584 = 38016
constexpr int SM_BYTES = 2 * STAGE;            // 76032 -> 2 CTAs/SM

constexpr int KBLOCKS = BH * S * DD / 8 / 256; // 1024 prep blocks for K
}

// prep scratch
__device__ __align__(16) __half gKh[BH * S * DD];
__device__ __align__(16) __half gVth[BH * D2 * S];   // [h][d][s], d in [0,72)

// ---------------- asm helpers ----------------
__device__ __forceinline__ uint32_t smem_u32(const void* p) {
    uint32_t a;
    asm("{ .reg .u64 t; cvta.to.shared.u64 t, %1; cvt.u32.u64 %0, t; }" : "=r"(a) : "l"(p));
    return a;
}
__device__ __forceinline__ float ex2f(float x) {
    float r;
    asm("ex2.approx.f32 %0, %1;" : "=f"(r) : "f"(x));
    return r;
}

#define MMA_F16(c, a, b0_, b1_)                                                    \
    asm volatile("mma.sync.aligned.m16n8k16.row.col.f32.f16.f16.f32 "              \
                 "{%0,%1,%2,%3},{%4,%5,%6,%7},{%8,%9},{%0,%1,%2,%3};"              \
                 : "+f"((c)[0]), "+f"((c)[1]), "+f"((c)[2]), "+f"((c)[3])          \
                 : "r"((a)[0]), "r"((a)[1]), "r"((a)[2]), "r"((a)[3]),             \
                   "r"(b0_), "r"(b1_))

#define LDSM4(r, addr)                                                             \
    asm volatile("ldmatrix.sync.aligned.m8n8.x4.shared.b16 {%0,%1,%2,%3}, [%4];"   \
                 : "=r"((r)[0]), "=r"((r)[1]), "=r"((r)[2]), "=r"((r)[3])          \
                 : "r"(addr))

#define LDSM2(r0, r1, addr)                                                        \
    asm volatile("ldmatrix.sync.aligned.m8n8.x2.shared.b16 {%0,%1}, [%2];"         \
                 : "=r"(r0), "=r"(r1) : "r"(addr))

#define CP16(dst, src)                                                             \
    asm volatile("cp.async.cg.shared.global [%0], [%1], 16;" :: "r"(dst), "l"(src))
#define CP_COMMIT() asm volatile("cp.async.commit_group;" ::: "memory")
#define CP_WAIT0()  asm volatile("cp.async.wait_group 0;" ::: "memory")

// ldmatrix x4 lane address (pitch P): 4 8x8 mats (n0,k),(n0,k+8),(n0+8,k),(n0+8,k+8)
template <int P>
__device__ __forceinline__ uint32_t ldsm_addr(uint32_t base, int n0, int kel, int lane) {
    int gq = lane >> 3, lr = lane & 7;
    int row = n0 + lr + ((gq & 2) << 2);
    int col = kel + ((gq & 1) << 3);
    return base + row * P + col * 2;
}
// ldmatrix x2 lane address: (row0..row0+8) x (kel, kel+8), pitch VROWB
__device__ __forceinline__ uint32_t ldsm_addr2(uint32_t base, int row0, int kel, int lane) {
    int row = row0 + (lane & 7);
    int col = kel + ((lane >> 3) & 1) * 8;
    return base + row * VROWB + col * 2;
}

__device__ __forceinline__ uint32_t pack_h2(float x, float y) {
    __half2 t = __floats2half2_rn(x, y);
    return *reinterpret_cast<uint32_t*>(&t);
}

// ---------------- merged prep ----------------
// blocks [0, KBLOCKS):    K fp32 -> fp16 (8 elems/thread)
// blocks [KBLOCKS, +512): Vt[d][s] = w_s*V[s][d]; row 64 = w_s; rows 65..71 = 0
__global__ __launch_bounds__(256)
void prep_all(const float* __restrict__ K, const float* __restrict__ V,
              const float* __restrict__ C)
{
    __shared__ float sm[64 * 65];
    __shared__ float ws[64];

    if (blockIdx.x < KBLOCKS) {
        int idx = blockIdx.x * 256 + threadIdx.x;
        const float4* src = (const float4*)K + idx * 2;
        float4 a = src[0], b = src[1];
        uint4 o;
        o.x = pack_h2(a.x, a.y);
        o.y = pack_h2(a.z, a.w);
        o.z = pack_h2(b.x, b.y);
        o.w = pack_h2(b.z, b.w);
        *((uint4*)gKh + idx) = o;
        return;
    }

    int vb = blockIdx.x - KBLOCKS;          // 0..511
    int head = vb >> 5, s0 = (vb & 31) * 64;
    const float* src = V + (head * S + s0) * DD;
    for (int i = threadIdx.x; i < 1024; i += 256) {    // float4 index
        int r = i >> 4, c4 = (i & 15) * 4;
        float4 v = *(const float4*)(src + r * DD + c4);
        sm[(c4 + 0) * 65 + r] = v.x;
        sm[(c4 + 1) * 65 + r] = v.y;
        sm[(c4 + 2) * 65 + r] = v.z;
        sm[(c4 + 3) * 65 + r] = v.w;
    }
    if (threadIdx.x < 64) {
        int s = s0 + threadIdx.x;
        ws[threadIdx.x] = (s == 0) ? 0.f : fabsf(C[s] - C[s - 1]);
    }
    __syncthreads();
    for (int i = threadIdx.x; i < D2 * 16; i += 256) {  // 4-half units
        int d = i >> 4, c4 = (i & 15) * 4;
        uint2 o;
        if (d < 64) {
            const float* row = &sm[d * 65 + c4];
            o.x = pack_h2(row[0] * ws[c4], row[1] * ws[c4 + 1]);
            o.y = pack_h2(row[2] * ws[c4 + 2], row[3] * ws[c4 + 3]);
        } else if (d == 64) {
            o.x = pack_h2(ws[c4], ws[c4 + 1]);
            o.y = pack_h2(ws[c4 + 2], ws[c4 + 3]);
        } else {
            o.x = 0u; o.y = 0u;
        }
        *(uint2*)(gVth + ((size_t)head * D2 + d) * S + s0 + c4) = o;
    }
}

// ---------------- main kernel: 4 warps, M=32 rows per warp ----------------
__global__ __launch_bounds__(128, 2)
void attn_mma_kernel(const float* __restrict__ Q, float* __restrict__ O)
{
    extern __shared__ char smc[];
    const uint32_t sb = smem_u32(smc);
    const int tid  = threadIdx.x;
    const int lane = tid & 31;
    const int warp = tid >> 5;
    const int head = blockIdx.y;
    const int qtile = blockIdx.x;

    const int g  = lane >> 2;       // row within m8 group
    const int tq = lane & 3;        // column quad

    const int qbase = qtile * QT + warp * 32;

    // ---- hoisted loader addressing (loop-invariant per thread) ----
    // K chunk i = it*128+tid: gmem byte = head*S*128 + t*KT*128 + i*16 (linear);
    //                         smem dst = (i>>3)*KROWB + (i&7)*16 = it*2304 + kdst0
    // V chunk j = it*128+tid: d = it*8 + (tid>>4), c = tid&15;
    //                         gmem = ((head*D2+d)*S + t*KT)*2 + c*16; dst = it*2176 + vdst0
    const char* kbase = (const char*)gKh + (size_t)head * S * 128 + tid * 16;
    const char* vbase = (const char*)gVth + (((size_t)head * D2 + (tid >> 4)) * S) * 2
                                          + (tid & 15) * 16;
    const uint32_t kdst0 = (tid >> 3) * KROWB + (tid & 7) * 16;
    const uint32_t vdst0 = (tid >> 4) * VROWB + (tid & 15) * 16;

    auto issue = [&](int t, uint32_t st) {
        const char* ks = kbase + (size_t)t * KT * 128;
        #pragma unroll
        for (int it = 0; it < 8; ++it)
            CP16(st + KH_OFF + kdst0 + it * 2304, ks + it * 2048);
        const char* vs = vbase + t * KT * 2;
        #pragma unroll
        for (int it = 0; it < 9; ++it)
            CP16(st + VH_OFF + vdst0 + it * 2176, vs + (size_t)it * 8 * S * 2);
    };

    issue(0, sb); CP_COMMIT();

    // ---- Q A-fragments for two m16 blocks, 0.125*log2(e) folded ----
    uint32_t qh[2][4][4];
    {
        constexpr float SC = 0.125f * 1.4426950408889634f;
        #pragma unroll
        for (int r = 0; r < 2; ++r) {
            const float* q0 = Q + (size_t)(head * L + qbase + r * 16 + g) * DD;
            const float* q8 = q0 + 8 * DD;
            #pragma unroll
            for (int ks = 0; ks < 4; ++ks) {
                int cb = ks * 16 + tq * 2;
                float2 a0 = *(const float2*)(q0 + cb);
                float2 a1 = *(const float2*)(q8 + cb);
                float2 a2 = *(const float2*)(q0 + cb + 8);
                float2 a3 = *(const float2*)(q8 + cb + 8);
                qh[r][ks][0] = pack_h2(a0.x * SC, a0.y * SC);
                qh[r][ks][1] = pack_h2(a1.x * SC, a1.y * SC);
                qh[r][ks][2] = pack_h2(a2.x * SC, a2.y * SC);
                qh[r][ks][3] = pack_h2(a3.x * SC, a3.y * SC);
            }
        }
    }

    float o_acc[2][8][4];
    #pragma unroll
    for (int r = 0; r < 2; ++r)
        #pragma unroll
        for (int i = 0; i < 8; ++i)
            #pragma unroll
            for (int j = 0; j < 4; ++j) o_acc[r][i][j] = 0.f;
    float dacc[2][4];
    #pragma unroll
    for (int r = 0; r < 2; ++r)
        #pragma unroll
        for (int j = 0; j < 4; ++j) dacc[r][j] = 0.f;

    for (int t = 0; t < NT; ++t) {
        CP_WAIT0();            // stage t&1 loaded
        __syncthreads();       // all warps done with stage (t+1)&1 (from t-1)

        if (t + 1 < NT) { issue(t + 1, sb + ((t + 1) & 1) * STAGE); CP_COMMIT(); }

        const uint32_t st = sb + (t & 1) * STAGE;

        #pragma unroll
        for (int kc = 0; kc < 8; ++kc) {
            // ---- GEMM1: scores (fp16, exp2 domain), keys [16kc,16kc+16) ----
            float sc[2][2][4];
            #pragma unroll
            for (int r = 0; r < 2; ++r)
                #pragma unroll
                for (int hnf = 0; hnf < 2; ++hnf)
                    #pragma unroll
                    for (int j = 0; j < 4; ++j) sc[r][hnf][j] = 0.f;

            #pragma unroll
            for (int ks = 0; ks < 4; ++ks) {
                uint32_t bh[4];
                LDSM4(bh, ldsm_addr<KROWB>(st + KH_OFF, 16 * kc, ks * 16, lane));
                #pragma unroll
                for (int r = 0; r < 2; ++r) {
                    MMA_F16(sc[r][0], qh[r][ks], bh[0], bh[1]);
                    MMA_F16(sc[r][1], qh[r][ks], bh[2], bh[3]);
                }
            }

            // ---- p = ex2(s): fp16 A-frags (w already folded into V) ----
            uint32_t aH[2][4];
            #pragma unroll
            for (int r = 0; r < 2; ++r) {
                aH[r][0] = pack_h2(ex2f(sc[r][0][0]), ex2f(sc[r][0][1]));
                aH[r][1] = pack_h2(ex2f(sc[r][0][2]), ex2f(sc[r][0][3]));
                aH[r][2] = pack_h2(ex2f(sc[r][1][0]), ex2f(sc[r][1][1]));
                aH[r][3] = pack_h2(ex2f(sc[r][1][2]), ex2f(sc[r][1][3]));
            }

            // ---- GEMM2: O += P * Vt' ----
            #pragma unroll
            for (int nd = 0; nd < 4; ++nd) {
                uint32_t vh[4];
                LDSM4(vh, ldsm_addr<VROWB>(st + VH_OFF, 16 * nd, 16 * kc, lane));
                #pragma unroll
                for (int r = 0; r < 2; ++r) {
                    MMA_F16(o_acc[r][2 * nd],     aH[r], vh[0], vh[1]);
                    MMA_F16(o_acc[r][2 * nd + 1], aH[r], vh[2], vh[3]);
                }
            }
            // ---- denominator: extra n=8 block, Vt row 64 = w ----
            {
                uint32_t w0, w1;
                LDSM2(w0, w1, ldsm_addr2(st + VH_OFF, 64, 16 * kc, lane));
                MMA_F16(dacc[0], aH[0], w0, w1);
                MMA_F16(dacc[1], aH[1], w0, w1);
            }
        }
    }

    // ---- den broadcast from quad leader (col 64 lives at tq==0) + store ----
    #pragma unroll
    for (int r = 0; r < 2; ++r) {
        float den0 = __shfl_sync(0xffffffffu, dacc[r][0], lane & 0x1C);
        float den1 = __shfl_sync(0xffffffffu, dacc[r][2], lane & 0x1C);
        float inv0 = 1.0f / den0;
        float inv1 = 1.0f / den1;
        float* dst0 = O + (size_t)(head * L + qbase + r * 16 + g) * DD;
        float* dst1 = dst0 + 8 * DD;
        #pragma unroll
        for (int nf = 0; nf < 8; ++nf) {
            int col = nf * 8 + tq * 2;
            float2 r0, r1;
            r0.x = o_acc[r][nf][0] * inv0; r0.y = o_acc[r][nf][1] * inv0;
            r1.x = o_acc[r][nf][2] * inv1; r1.y = o_acc[r][nf][3] * inv1;
            *(float2*)(dst0 + col) = r0;
            *(float2*)(dst1 + col) = r1;
        }
    }
}

extern "C" void kernel_launch(void* const* d_in, const int* in_sizes, int n_in,
                              void* d_out, int out_size)
{
    const float* Q = (const float*)d_in[0];
    const float* K = (const float*)d_in[1];
    const float* V = (const float*)d_in[2];
    const float* C = (const float*)d_in[3];
    float* O = (float*)d_out;

    prep_all<<<KBLOCKS + 512, 256>>>(K, V, C);

    cudaFuncSetAttribute(attn_mma_kernel,
                         cudaFuncAttributeMaxDynamicSharedMemorySize, SM_BYTES);
    attn_mma_kernel<<<dim3(L / QT, BH), 128, SM_BYTES>>>(Q, O);
}

// round 13
// speedup vs baseline: 1.1923x; 1.0429x over previous
#include <cuda_runtime.h>
#include <cuda_fp16.h>
#include <cstdint>

// Coords-weighted softmax attention via mma.sync m16n8k16 fp16 (sm_100 base ISA).
// R13 = R9 base (best: 62.3us; M=32/warp, QT=128, KT=64, 3-stage, w-folded V,
// denominator via w-row MMA) + ex2.approx.f16x2 softmax:
//   scores packed fp32->half2 (cvt.rn.f16x2.f32, needed anyway), then ONE
//   f16x2 ex2 per pair -> MUFU instruction stream halved (XU ~18us -> ~9us,
//   nearly co-binding with the 34.8us tensor floor at HMMA rt=8).
// den-MMA consumes the identical fp16 p-values as the numerator (correlated
// rounding, like the reference's shared exp_x).

namespace {
constexpr int BH = 16, L = 2048, S = 2048, DD = 64;
constexpr int QT = 128;            // queries per CTA
constexpr int KT = 64;             // keys per tile
constexpr int NT = S / KT;         // 32
constexpr int NSTAGE = 3;
constexpr int D2 = 72;             // Vt rows: 64 d + w row + 7 zero

constexpr int ROWB = 144;          // smem row pitch bytes (128B data + 16B skew)

constexpr int KH_OFF = 0;
constexpr int VH_OFF = KH_OFF + KT * ROWB;    //  9216
constexpr int STAGE  = VH_OFF + D2 * ROWB;    // 19584
constexpr int SM_BYTES = NSTAGE * STAGE;      // 58752

constexpr int KBLOCKS = BH * S * DD / 8 / 256;  // 1024 prep blocks for K
}

// prep scratch
__device__ __align__(16) __half gKh[BH * S * DD];
__device__ __align__(16) __half gVth[BH * D2 * S];   // [h][d][s]

// ---------------- asm helpers ----------------
__device__ __forceinline__ uint32_t smem_u32(const void* p) {
    uint32_t a;
    asm("{ .reg .u64 t; cvta.to.shared.u64 t, %1; cvt.u32.u64 %0, t; }" : "=r"(a) : "l"(p));
    return a;
}

#define EX2_H2(d, s) \
    asm("ex2.approx.f16x2 %0, %1;" : "=r"(d) : "r"(s))

#define MMA_F16(c, a, b0_, b1_)                                                    \
    asm volatile("mma.sync.aligned.m16n8k16.row.col.f32.f16.f16.f32 "              \
                 "{%0,%1,%2,%3},{%4,%5,%6,%7},{%8,%9},{%0,%1,%2,%3};"              \
                 : "+f"((c)[0]), "+f"((c)[1]), "+f"((c)[2]), "+f"((c)[3])          \
                 : "r"((a)[0]), "r"((a)[1]), "r"((a)[2]), "r"((a)[3]),             \
                   "r"(b0_), "r"(b1_))

#define LDSM4(r, addr)                                                             \
    asm volatile("ldmatrix.sync.aligned.m8n8.x4.shared.b16 {%0,%1,%2,%3}, [%4];"   \
                 : "=r"((r)[0]), "=r"((r)[1]), "=r"((r)[2]), "=r"((r)[3])          \
                 : "r"(addr))

#define LDSM2(r0, r1, addr)                                                        \
    asm volatile("ldmatrix.sync.aligned.m8n8.x2.shared.b16 {%0,%1}, [%2];"         \
                 : "=r"(r0), "=r"(r1) : "r"(addr))

#define CP16(dst, src)                                                             \
    asm volatile("cp.async.cg.shared.global [%0], [%1], 16;" :: "r"(dst), "l"(src))
#define CP16P(dst, src, pred)                                                      \
    asm volatile("{ .reg .pred p; setp.ne.u32 p, %2, 0;"                           \
                 "@p cp.async.cg.shared.global [%0], [%1], 16; }"                  \
                 :: "r"(dst), "l"(src), "r"(pred))
#define CP_COMMIT() asm volatile("cp.async.commit_group;" ::: "memory")
#define CP_WAIT1()  asm volatile("cp.async.wait_group 1;" ::: "memory")
#define CP_WAIT0()  asm volatile("cp.async.wait_group 0;" ::: "memory")

// ldmatrix x4 lane address: 4 8x8 matrices (n0,k),(n0,k+8),(n0+8,k),(n0+8,k+8)
__device__ __forceinline__ uint32_t ldsm_addr(uint32_t base, int n0, int kel, int lane) {
    int gq = lane >> 3, lr = lane & 7;
    int row = n0 + lr + ((gq & 2) << 2);
    int col = kel + ((gq & 1) << 3);
    return base + row * ROWB + col * 2;
}
// ldmatrix x2 lane address: matrices (row0..row0+8) x (kel, kel+8)
__device__ __forceinline__ uint32_t ldsm_addr2(uint32_t base, int row0, int kel, int lane) {
    int row = row0 + (lane & 7);
    int col = kel + ((lane >> 3) & 1) * 8;
    return base + row * ROWB + col * 2;
}

__device__ __forceinline__ uint32_t pack_h2(float x, float y) {
    __half2 t = __floats2half2_rn(x, y);
    return *reinterpret_cast<uint32_t*>(&t);
}

// ---------------- merged prep ----------------
// blocks [0, KBLOCKS):    K fp32 -> fp16 (8 elems/thread)
// blocks [KBLOCKS, +512): Vt[d][s] = w_s*V[s][d]; row 64 = w_s; rows 65..71 = 0
__global__ __launch_bounds__(256)
void prep_all(const float* __restrict__ K, const float* __restrict__ V,
              const float* __restrict__ C)
{
    __shared__ float sm[64 * 65];
    __shared__ float ws[64];

    if (blockIdx.x < KBLOCKS) {
        int idx = blockIdx.x * 256 + threadIdx.x;
        const float4* src = (const float4*)K + idx * 2;
        float4 a = src[0], b = src[1];
        uint4 o;
        o.x = pack_h2(a.x, a.y);
        o.y = pack_h2(a.z, a.w);
        o.z = pack_h2(b.x, b.y);
        o.w = pack_h2(b.z, b.w);
        *((uint4*)gKh + idx) = o;
        return;
    }

    int vb = blockIdx.x - KBLOCKS;          // 0..511
    int head = vb >> 5, s0 = (vb & 31) * 64;
    const float* src = V + (head * S + s0) * DD;
    for (int i = threadIdx.x; i < 1024; i += 256) {    // float4 index
        int r = i >> 4, c4 = (i & 15) * 4;
        float4 v = *(const float4*)(src + r * DD + c4);
        sm[(c4 + 0) * 65 + r] = v.x;
        sm[(c4 + 1) * 65 + r] = v.y;
        sm[(c4 + 2) * 65 + r] = v.z;
        sm[(c4 + 3) * 65 + r] = v.w;
    }
    if (threadIdx.x < 64) {
        int s = s0 + threadIdx.x;
        ws[threadIdx.x] = (s == 0) ? 0.f : fabsf(C[s] - C[s - 1]);
    }
    __syncthreads();
    for (int i = threadIdx.x; i < D2 * 16; i += 256) {  // 4-half units
        int d = i >> 4, c4 = (i & 15) * 4;
        uint2 o;
        if (d < 64) {
            const float* row = &sm[d * 65 + c4];
            o.x = pack_h2(row[0] * ws[c4], row[1] * ws[c4 + 1]);
            o.y = pack_h2(row[2] * ws[c4 + 2], row[3] * ws[c4 + 3]);
        } else if (d == 64) {
            o.x = pack_h2(ws[c4], ws[c4 + 1]);
            o.y = pack_h2(ws[c4 + 2], ws[c4 + 3]);
        } else {
            o.x = 0u; o.y = 0u;
        }
        *(uint2*)(gVth + ((size_t)head * D2 + d) * S + s0 + c4) = o;
    }
}

// ---------------- main kernel: 4 warps, M=32 rows per warp ----------------
__global__ __launch_bounds__(128, 2)
void attn_mma_kernel(const float* __restrict__ Q, float* __restrict__ O)
{
    extern __shared__ char smc[];
    const uint32_t sb = smem_u32(smc);
    const int tid  = threadIdx.x;
    const int lane = tid & 31;
    const int warp = tid >> 5;
    const int head = blockIdx.y;
    const int qtile = blockIdx.x;

    const int g  = lane >> 2;       // row within m8 group
    const int tq = lane & 3;        // column quad

    const int qbase = qtile * QT + warp * 32;

    // ---- async tile loader (Kh, Vt') into stage t%3 ----
    auto issue = [&](int t) {
        const uint32_t st = sb + (t % NSTAGE) * STAGE;
        const int s0 = t * KT;
        const char* kh = (const char*)(gKh + (size_t)(head * S + s0) * DD);
        #pragma unroll
        for (int it = 0; it < 4; ++it) {
            int i = it * 128 + tid;                 // 0..511 16B chunks (K)
            uint32_t dst = (i >> 3) * ROWB + (i & 7) * 16;
            CP16(st + KH_OFF + dst, kh + i * 16);
        }
        #pragma unroll
        for (int it = 0; it < 5; ++it) {
            int i = it * 128 + tid;                 // 0..575 chunks (V, 72 rows)
            uint32_t ok = (i < D2 * 8) ? 1u : 0u;
            int d = i >> 3, c = i & 7;
            size_t vsrc = (((size_t)head * D2 + d) * S + s0) * 2 + c * 16;
            uint32_t dst = d * ROWB + c * 16;
            CP16P(st + VH_OFF + dst, (const char*)gVth + vsrc, ok);
        }
    };

    issue(0); CP_COMMIT();

    // ---- Q A-fragments for two m16 blocks, 0.125*log2(e) folded ----
    uint32_t qh[2][4][4];
    {
        constexpr float SC = 0.125f * 1.4426950408889634f;
        #pragma unroll
        for (int r = 0; r < 2; ++r) {
            const float* q0 = Q + (size_t)(head * L + qbase + r * 16 + g) * DD;
            const float* q8 = q0 + 8 * DD;
            #pragma unroll
            for (int ks = 0; ks < 4; ++ks) {
                int cb = ks * 16 + tq * 2;
                float2 a0 = *(const float2*)(q0 + cb);
                float2 a1 = *(const float2*)(q8 + cb);
                float2 a2 = *(const float2*)(q0 + cb + 8);
                float2 a3 = *(const float2*)(q8 + cb + 8);
                qh[r][ks][0] = pack_h2(a0.x * SC, a0.y * SC);
                qh[r][ks][1] = pack_h2(a1.x * SC, a1.y * SC);
                qh[r][ks][2] = pack_h2(a2.x * SC, a2.y * SC);
                qh[r][ks][3] = pack_h2(a3.x * SC, a3.y * SC);
            }
        }
    }

    issue(1); CP_COMMIT();

    float o_acc[2][8][4];
    #pragma unroll
    for (int r = 0; r < 2; ++r)
        #pragma unroll
        for (int i = 0; i < 8; ++i)
            #pragma unroll
            for (int j = 0; j < 4; ++j) o_acc[r][i][j] = 0.f;
    float dacc[2][4];
    #pragma unroll
    for (int r = 0; r < 2; ++r)
        #pragma unroll
        for (int j = 0; j < 4; ++j) dacc[r][j] = 0.f;

    for (int t = 0; t < NT; ++t) {
        if (t == NT - 1) { CP_WAIT0(); } else { CP_WAIT1(); }
        __syncthreads();   // stage t ready, stage (t+2)%3 free

        const uint32_t st = sb + (t % NSTAGE) * STAGE;

        #pragma unroll
        for (int kc = 0; kc < 4; ++kc) {
            // ---- GEMM1: scores (fp16, exp2 domain), keys [16kc,16kc+16) ----
            float sc[2][2][4];
            #pragma unroll
            for (int r = 0; r < 2; ++r)
                #pragma unroll
                for (int hnf = 0; hnf < 2; ++hnf)
                    #pragma unroll
                    for (int j = 0; j < 4; ++j) sc[r][hnf][j] = 0.f;

            #pragma unroll
            for (int ks = 0; ks < 4; ++ks) {
                uint32_t bh[4];
                LDSM4(bh, ldsm_addr(st + KH_OFF, 16 * kc, ks * 16, lane));
                #pragma unroll
                for (int r = 0; r < 2; ++r) {
                    MMA_F16(sc[r][0], qh[r][ks], bh[0], bh[1]);
                    MMA_F16(sc[r][1], qh[r][ks], bh[2], bh[3]);
                }
            }

            // ---- p = ex2.f16x2(s): pack score pairs then ONE f16x2 ex2 each ----
            uint32_t aH[2][4];
            #pragma unroll
            for (int r = 0; r < 2; ++r) {
                uint32_t s0 = pack_h2(sc[r][0][0], sc[r][0][1]);
                uint32_t s1 = pack_h2(sc[r][0][2], sc[r][0][3]);
                uint32_t s2 = pack_h2(sc[r][1][0], sc[r][1][1]);
                uint32_t s3 = pack_h2(sc[r][1][2], sc[r][1][3]);
                EX2_H2(aH[r][0], s0);
                EX2_H2(aH[r][1], s1);
                EX2_H2(aH[r][2], s2);
                EX2_H2(aH[r][3], s3);
            }

            // ---- GEMM2: O += P * Vt' (w folded into V) ----
            #pragma unroll
            for (int nd = 0; nd < 4; ++nd) {
                uint32_t vh[4];
                LDSM4(vh, ldsm_addr(st + VH_OFF, 16 * nd, 16 * kc, lane));
                #pragma unroll
                for (int r = 0; r < 2; ++r) {
                    MMA_F16(o_acc[r][2 * nd],     aH[r], vh[0], vh[1]);
                    MMA_F16(o_acc[r][2 * nd + 1], aH[r], vh[2], vh[3]);
                }
            }
            // ---- denominator: extra n=8 block, Vt row 64 = w ----
            {
                uint32_t w0, w1;
                LDSM2(w0, w1, ldsm_addr2(st + VH_OFF, 64, 16 * kc, lane));
                MMA_F16(dacc[0], aH[0], w0, w1);
                MMA_F16(dacc[1], aH[1], w0, w1);
            }
        }

        if (t + 2 < NT) { issue(t + 2); CP_COMMIT(); }
    }

    // ---- den broadcast from quad leader (col 64 lives at tq==0) + store ----
    #pragma unroll
    for (int r = 0; r < 2; ++r) {
        float den0 = __shfl_sync(0xffffffffu, dacc[r][0], lane & 0x1C);
        float den1 = __shfl_sync(0xffffffffu, dacc[r][2], lane & 0x1C);
        float inv0 = 1.0f / den0;
        float inv1 = 1.0f / den1;
        float* dst0 = O + (size_t)(head * L + qbase + r * 16 + g) * DD;
        float* dst1 = dst0 + 8 * DD;
        #pragma unroll
        for (int nf = 0; nf < 8; ++nf) {
            int col = nf * 8 + tq * 2;
            float2 r0, r1;
            r0.x = o_acc[r][nf][0] * inv0; r0.y = o_acc[r][nf][1] * inv0;
            r1.x = o_acc[r][nf][2] * inv1; r1.y = o_acc[r][nf][3] * inv1;
            *(float2*)(dst0 + col) = r0;
            *(float2*)(dst1 + col) = r1;
        }
    }
}

extern "C" void kernel_launch(void* const* d_in, const int* in_sizes, int n_in,
                              void* d_out, int out_size)
{
    const float* Q = (const float*)d_in[0];
    const float* K = (const float*)d_in[1];
    const float* V = (const float*)d_in[2];
    const float* C = (const float*)d_in[3];
    float* O = (float*)d_out;

    prep_all<<<KBLOCKS + 512, 256>>>(K, V, C);

    cudaFuncSetAttribute(attn_mma_kernel,
                         cudaFuncAttributeMaxDynamicSharedMemorySize, SM_BYTES);
    attn_mma_kernel<<<dim3(L / QT, BH), 128, SM_BYTES>>>(Q, O);
}

// round 14
// speedup vs baseline: 1.2405x; 1.0403x over previous
#include <cuda_runtime.h>
#include <cuda_fp16.h>
#include <cstdint>

// Coords-weighted softmax attention via mma.sync m16n8k16 fp16 (sm_100 base ISA).
// R14 = R13 (best: 61.9us) + software-pipelined kc loop:
//   GEMM1(kc+1) issued between exp(kc) and GEMM2(kc) -- the tensor pipe chews
//   independent score MMAs while the cvt/ex2 chain for kc resolves, hiding the
//   serial GEMM1->exp->GEMM2 dependency that left the pipe 42% idle (issue=25%).
//   Double-buffered score accumulators (sc[2][...]) carry the overlap.
// Math unchanged: 1/8*log2(e) folded into Q, ex2.approx.f16x2 softmax,
// w folded into V' = w*V, Vt row 64 = w -> denominator via one n=8 MMA.

namespace {
constexpr int BH = 16, L = 2048, S = 2048, DD = 64;
constexpr int QT = 128;            // queries per CTA
constexpr int KT = 64;             // keys per tile
constexpr int NT = S / KT;         // 32
constexpr int NSTAGE = 3;
constexpr int D2 = 72;             // Vt rows: 64 d + w row + 7 zero

constexpr int ROWB = 144;          // smem row pitch bytes (128B data + 16B skew)

constexpr int KH_OFF = 0;
constexpr int VH_OFF = KH_OFF + KT * ROWB;    //  9216
constexpr int STAGE  = VH_OFF + D2 * ROWB;    // 19584
constexpr int SM_BYTES = NSTAGE * STAGE;      // 58752

constexpr int KBLOCKS = BH * S * DD / 8 / 256;  // 1024 prep blocks for K
}

// prep scratch
__device__ __align__(16) __half gKh[BH * S * DD];
__device__ __align__(16) __half gVth[BH * D2 * S];   // [h][d][s]

// ---------------- asm helpers ----------------
__device__ __forceinline__ uint32_t smem_u32(const void* p) {
    uint32_t a;
    asm("{ .reg .u64 t; cvta.to.shared.u64 t, %1; cvt.u32.u64 %0, t; }" : "=r"(a) : "l"(p));
    return a;
}

#define EX2_H2(d, s) \
    asm("ex2.approx.f16x2 %0, %1;" : "=r"(d) : "r"(s))

#define MMA_F16(c, a, b0_, b1_)                                                    \
    asm volatile("mma.sync.aligned.m16n8k16.row.col.f32.f16.f16.f32 "              \
                 "{%0,%1,%2,%3},{%4,%5,%6,%7},{%8,%9},{%0,%1,%2,%3};"              \
                 : "+f"((c)[0]), "+f"((c)[1]), "+f"((c)[2]), "+f"((c)[3])          \
                 : "r"((a)[0]), "r"((a)[1]), "r"((a)[2]), "r"((a)[3]),             \
                   "r"(b0_), "r"(b1_))

#define LDSM4(r, addr)                                                             \
    asm volatile("ldmatrix.sync.aligned.m8n8.x4.shared.b16 {%0,%1,%2,%3}, [%4];"   \
                 : "=r"((r)[0]), "=r"((r)[1]), "=r"((r)[2]), "=r"((r)[3])          \
                 : "r"(addr))

#define LDSM2(r0, r1, addr)                                                        \
    asm volatile("ldmatrix.sync.aligned.m8n8.x2.shared.b16 {%0,%1}, [%2];"         \
                 : "=r"(r0), "=r"(r1) : "r"(addr))

#define CP16(dst, src)                                                             \
    asm volatile("cp.async.cg.shared.global [%0], [%1], 16;" :: "r"(dst), "l"(src))
#define CP16P(dst, src, pred)                                                      \
    asm volatile("{ .reg .pred p; setp.ne.u32 p, %2, 0;"                           \
                 "@p cp.async.cg.shared.global [%0], [%1], 16; }"                  \
                 :: "r"(dst), "l"(src), "r"(pred))
#define CP_COMMIT() asm volatile("cp.async.commit_group;" ::: "memory")
#define CP_WAIT1()  asm volatile("cp.async.wait_group 1;" ::: "memory")
#define CP_WAIT0()  asm volatile("cp.async.wait_group 0;" ::: "memory")

// ldmatrix x4 lane address: 4 8x8 matrices (n0,k),(n0,k+8),(n0+8,k),(n0+8,k+8)
__device__ __forceinline__ uint32_t ldsm_addr(uint32_t base, int n0, int kel, int lane) {
    int gq = lane >> 3, lr = lane & 7;
    int row = n0 + lr + ((gq & 2) << 2);
    int col = kel + ((gq & 1) << 3);
    return base + row * ROWB + col * 2;
}
// ldmatrix x2 lane address: matrices (row0..row0+8) x (kel, kel+8)
__device__ __forceinline__ uint32_t ldsm_addr2(uint32_t base, int row0, int kel, int lane) {
    int row = row0 + (lane & 7);
    int col = kel + ((lane >> 3) & 1) * 8;
    return base + row * ROWB + col * 2;
}

__device__ __forceinline__ uint32_t pack_h2(float x, float y) {
    __half2 t = __floats2half2_rn(x, y);
    return *reinterpret_cast<uint32_t*>(&t);
}

// ---------------- merged prep ----------------
// blocks [0, KBLOCKS):    K fp32 -> fp16 (8 elems/thread)
// blocks [KBLOCKS, +512): Vt[d][s] = w_s*V[s][d]; row 64 = w_s; rows 65..71 = 0
__global__ __launch_bounds__(256)
void prep_all(const float* __restrict__ K, const float* __restrict__ V,
              const float* __restrict__ C)
{
    __shared__ float sm[64 * 65];
    __shared__ float ws[64];

    if (blockIdx.x < KBLOCKS) {
        int idx = blockIdx.x * 256 + threadIdx.x;
        const float4* src = (const float4*)K + idx * 2;
        float4 a = src[0], b = src[1];
        uint4 o;
        o.x = pack_h2(a.x, a.y);
        o.y = pack_h2(a.z, a.w);
        o.z = pack_h2(b.x, b.y);
        o.w = pack_h2(b.z, b.w);
        *((uint4*)gKh + idx) = o;
        return;
    }

    int vb = blockIdx.x - KBLOCKS;          // 0..511
    int head = vb >> 5, s0 = (vb & 31) * 64;
    const float* src = V + (head * S + s0) * DD;
    for (int i = threadIdx.x; i < 1024; i += 256) {    // float4 index
        int r = i >> 4, c4 = (i & 15) * 4;
        float4 v = *(const float4*)(src + r * DD + c4);
        sm[(c4 + 0) * 65 + r] = v.x;
        sm[(c4 + 1) * 65 + r] = v.y;
        sm[(c4 + 2) * 65 + r] = v.z;
        sm[(c4 + 3) * 65 + r] = v.w;
    }
    if (threadIdx.x < 64) {
        int s = s0 + threadIdx.x;
        ws[threadIdx.x] = (s == 0) ? 0.f : fabsf(C[s] - C[s - 1]);
    }
    __syncthreads();
    for (int i = threadIdx.x; i < D2 * 16; i += 256) {  // 4-half units
        int d = i >> 4, c4 = (i & 15) * 4;
        uint2 o;
        if (d < 64) {
            const float* row = &sm[d * 65 + c4];
            o.x = pack_h2(row[0] * ws[c4], row[1] * ws[c4 + 1]);
            o.y = pack_h2(row[2] * ws[c4 + 2], row[3] * ws[c4 + 3]);
        } else if (d == 64) {
            o.x = pack_h2(ws[c4], ws[c4 + 1]);
            o.y = pack_h2(ws[c4 + 2], ws[c4 + 3]);
        } else {
            o.x = 0u; o.y = 0u;
        }
        *(uint2*)(gVth + ((size_t)head * D2 + d) * S + s0 + c4) = o;
    }
}

// ---------------- main kernel: 4 warps, M=32 rows per warp ----------------
__global__ __launch_bounds__(128, 2)
void attn_mma_kernel(const float* __restrict__ Q, float* __restrict__ O)
{
    extern __shared__ char smc[];
    const uint32_t sb = smem_u32(smc);
    const int tid  = threadIdx.x;
    const int lane = tid & 31;
    const int warp = tid >> 5;
    const int head = blockIdx.y;
    const int qtile = blockIdx.x;

    const int g  = lane >> 2;       // row within m8 group
    const int tq = lane & 3;        // column quad

    const int qbase = qtile * QT + warp * 32;

    // ---- async tile loader (Kh, Vt') into stage t%3 ----
    auto issue = [&](int t) {
        const uint32_t st = sb + (t % NSTAGE) * STAGE;
        const int s0 = t * KT;
        const char* kh = (const char*)(gKh + (size_t)(head * S + s0) * DD);
        #pragma unroll
        for (int it = 0; it < 4; ++it) {
            int i = it * 128 + tid;                 // 0..511 16B chunks (K)
            uint32_t dst = (i >> 3) * ROWB + (i & 7) * 16;
            CP16(st + KH_OFF + dst, kh + i * 16);
        }
        #pragma unroll
        for (int it = 0; it < 5; ++it) {
            int i = it * 128 + tid;                 // 0..575 chunks (V, 72 rows)
            uint32_t ok = (i < D2 * 8) ? 1u : 0u;
            int d = i >> 3, c = i & 7;
            size_t vsrc = (((size_t)head * D2 + d) * S + s0) * 2 + c * 16;
            uint32_t dst = d * ROWB + c * 16;
            CP16P(st + VH_OFF + dst, (const char*)gVth + vsrc, ok);
        }
    };

    issue(0); CP_COMMIT();

    // ---- Q A-fragments for two m16 blocks, 0.125*log2(e) folded ----
    uint32_t qh[2][4][4];
    {
        constexpr float SC = 0.125f * 1.4426950408889634f;
        #pragma unroll
        for (int r = 0; r < 2; ++r) {
            const float* q0 = Q + (size_t)(head * L + qbase + r * 16 + g) * DD;
            const float* q8 = q0 + 8 * DD;
            #pragma unroll
            for (int ks = 0; ks < 4; ++ks) {
                int cb = ks * 16 + tq * 2;
                float2 a0 = *(const float2*)(q0 + cb);
                float2 a1 = *(const float2*)(q8 + cb);
                float2 a2 = *(const float2*)(q0 + cb + 8);
                float2 a3 = *(const float2*)(q8 + cb + 8);
                qh[r][ks][0] = pack_h2(a0.x * SC, a0.y * SC);
                qh[r][ks][1] = pack_h2(a1.x * SC, a1.y * SC);
                qh[r][ks][2] = pack_h2(a2.x * SC, a2.y * SC);
                qh[r][ks][3] = pack_h2(a3.x * SC, a3.y * SC);
            }
        }
    }

    issue(1); CP_COMMIT();

    float o_acc[2][8][4];
    #pragma unroll
    for (int r = 0; r < 2; ++r)
        #pragma unroll
        for (int i = 0; i < 8; ++i)
            #pragma unroll
            for (int j = 0; j < 4; ++j) o_acc[r][i][j] = 0.f;
    float dacc[2][4];
    #pragma unroll
    for (int r = 0; r < 2; ++r)
        #pragma unroll
        for (int j = 0; j < 4; ++j) dacc[r][j] = 0.f;

    // double-buffered score accumulators for the kc software pipeline
    float sc[2][2][2][4];   // [buf][r][n-half][4]

    // GEMM1 for key chunk kc of the current tile into sc[buf]
    auto gemm1 = [&](uint32_t st, int kc, int buf) {
        #pragma unroll
        for (int r = 0; r < 2; ++r)
            #pragma unroll
            for (int hnf = 0; hnf < 2; ++hnf)
                #pragma unroll
                for (int j = 0; j < 4; ++j) sc[buf][r][hnf][j] = 0.f;
        #pragma unroll
        for (int ks = 0; ks < 4; ++ks) {
            uint32_t bh[4];
            LDSM4(bh, ldsm_addr(st + KH_OFF, 16 * kc, ks * 16, lane));
            #pragma unroll
            for (int r = 0; r < 2; ++r) {
                MMA_F16(sc[buf][r][0], qh[r][ks], bh[0], bh[1]);
                MMA_F16(sc[buf][r][1], qh[r][ks], bh[2], bh[3]);
            }
        }
    };

    for (int t = 0; t < NT; ++t) {
        if (t == NT - 1) { CP_WAIT0(); } else { CP_WAIT1(); }
        __syncthreads();   // stage t ready, stage (t+2)%3 free

        const uint32_t st = sb + (t % NSTAGE) * STAGE;

        gemm1(st, 0, 0);   // prologue: scores for kc=0

        #pragma unroll
        for (int kc = 0; kc < 4; ++kc) {
            const int buf = kc & 1;

            // ---- p = ex2.f16x2(sc[buf]) (XU chain for this kc) ----
            uint32_t aH[2][4];
            #pragma unroll
            for (int r = 0; r < 2; ++r) {
                uint32_t s0 = pack_h2(sc[buf][r][0][0], sc[buf][r][0][1]);
                uint32_t s1 = pack_h2(sc[buf][r][0][2], sc[buf][r][0][3]);
                uint32_t s2 = pack_h2(sc[buf][r][1][0], sc[buf][r][1][1]);
                uint32_t s3 = pack_h2(sc[buf][r][1][2], sc[buf][r][1][3]);
                EX2_H2(aH[r][0], s0);
                EX2_H2(aH[r][1], s1);
                EX2_H2(aH[r][2], s2);
                EX2_H2(aH[r][3], s3);
            }

            // ---- GEMM1 for kc+1: independent tensor work that hides the
            //      cvt/ex2 chain above (and aH's scoreboard wait below) ----
            if (kc < 3) gemm1(st, kc + 1, buf ^ 1);

            // ---- GEMM2: O += P * Vt' (w folded into V) ----
            #pragma unroll
            for (int nd = 0; nd < 4; ++nd) {
                uint32_t vh[4];
                LDSM4(vh, ldsm_addr(st + VH_OFF, 16 * nd, 16 * kc, lane));
                #pragma unroll
                for (int r = 0; r < 2; ++r) {
                    MMA_F16(o_acc[r][2 * nd],     aH[r], vh[0], vh[1]);
                    MMA_F16(o_acc[r][2 * nd + 1], aH[r], vh[2], vh[3]);
                }
            }
            // ---- denominator: extra n=8 block, Vt row 64 = w ----
            {
                uint32_t w0, w1;
                LDSM2(w0, w1, ldsm_addr2(st + VH_OFF, 64, 16 * kc, lane));
                MMA_F16(dacc[0], aH[0], w0, w1);
                MMA_F16(dacc[1], aH[1], w0, w1);
            }
        }

        if (t + 2 < NT) { issue(t + 2); CP_COMMIT(); }
    }

    // ---- den broadcast from quad leader (col 64 lives at tq==0) + store ----
    #pragma unroll
    for (int r = 0; r < 2; ++r) {
        float den0 = __shfl_sync(0xffffffffu, dacc[r][0], lane & 0x1C);
        float den1 = __shfl_sync(0xffffffffu, dacc[r][2], lane & 0x1C);
        float inv0 = 1.0f / den0;
        float inv1 = 1.0f / den1;
        float* dst0 = O + (size_t)(head * L + qbase + r * 16 + g) * DD;
        float* dst1 = dst0 + 8 * DD;
        #pragma unroll
        for (int nf = 0; nf < 8; ++nf) {
            int col = nf * 8 + tq * 2;
            float2 r0, r1;
            r0.x = o_acc[r][nf][0] * inv0; r0.y = o_acc[r][nf][1] * inv0;
            r1.x = o_acc[r][nf][2] * inv1; r1.y = o_acc[r][nf][3] * inv1;
            *(float2*)(dst0 + col) = r0;
            *(float2*)(dst1 + col) = r1;
        }
    }
}

extern "C" void kernel_launch(void* const* d_in, const int* in_sizes, int n_in,
                              void* d_out, int out_size)
{
    const float* Q = (const float*)d_in[0];
    const float* K = (const float*)d_in[1];
    const float* V = (const float*)d_in[2];
    const float* C = (const float*)d_in[3];
    float* O = (float*)d_out;

    prep_all<<<KBLOCKS + 512, 256>>>(K, V, C);

    cudaFuncSetAttribute(attn_mma_kernel,
                         cudaFuncAttributeMaxDynamicSharedMemorySize, SM_BYTES);
    attn_mma_kernel<<<dim3(L / QT, BH), 128, SM_BYTES>>>(Q, O);
}